// round 15
// baseline (speedup 1.0000x reference)
#include <cuda_runtime.h>
#include <math.h>

constexpr int Bq = 64, Fq = 256, Tq = 1024, Hq = 1024, Oq = 512;
constexpr int NB_RNN = 128;
constexpr int GRP = 32;       // CTAs per b-group barrier
constexpr int NTILES = 2048;  // 8 tb x 64 b x 4 o-blocks (phase-3 tiles)

// Scratch (allocations forbidden; __device__ globals are the sanctioned path)
__device__ float g_U[(size_t)Bq * Tq * Hq];   // (B, T, H) = x@Wx + b
__device__ float g_S[(size_t)Bq * Tq * Hq];   // (B, T, H) states
__device__ unsigned g_barArr[4 * 32];         // 4 group barriers, 128B apart
__device__ unsigned g_tile;                   // shared phase-3 tile queue

__global__ void reset_kernel() {
  if (threadIdx.x < 4 * 32) g_barArr[threadIdx.x] = 0u;
  if (threadIdx.x == 128) g_tile = 0u;
}
__global__ void dummy_kernel() {}  // keeps rnn in ncu's captured launch slot

// ---------------- packed fp32x2 helpers (sm_103a FFMA2 path) ----------------
using u64 = unsigned long long;
__device__ __forceinline__ u64 pack2(float lo, float hi) {
  u64 r; asm("mov.b64 %0, {%1,%2};" : "=l"(r) : "f"(lo), "f"(hi)); return r;
}
__device__ __forceinline__ u64 dup2(float v) { return pack2(v, v); }
__device__ __forceinline__ u64 ffma2(u64 a, u64 b, u64 c) {
  u64 d; asm("fma.rn.f32x2 %0, %1, %2, %3;" : "=l"(d) : "l"(a), "l"(b), "l"(c));
  return d;
}
__device__ __forceinline__ u64 fmul2(u64 a, u64 b) {
  u64 d; asm("mul.rn.f32x2 %0, %1, %2;" : "=l"(d) : "l"(a), "l"(b)); return d;
}
__device__ __forceinline__ u64 fadd2(u64 a, u64 b) {
  u64 d; asm("add.rn.f32x2 %0, %1, %2;" : "=l"(d) : "l"(a), "l"(b)); return d;
}
__device__ __forceinline__ void unpack2(u64 v, float& lo, float& hi) {
  asm("mov.b64 {%0,%1}, %2;" : "=f"(lo), "=f"(hi) : "l"(v));
}

// ---------------------------------------------------------------------------
// Tiled fp32 GEMM with bias, double-buffered smem (phase 1 only now).
// MODE 0: A[r][f] = x[b,f,t] gather (coalesced along t).
// ---------------------------------------------------------------------------
template <int MODE, int KDIM, int NDIM>
__global__ __launch_bounds__(256, 2) void gemm_bias_kernel(
    const float* __restrict__ A, const float* __restrict__ Bm,
    const float* __restrict__ bias, float* __restrict__ C) {
  __shared__ float sA[2][8][128];
  __shared__ float sB[2][8][128];
  const int tid = threadIdx.x;
  const int n0 = blockIdx.x * 128;
  const int m0 = blockIdx.y * 128;
  const int tx = tid & 15, ty = tid >> 4;
  const int ia = tid & 127, ja = tid >> 7;

  float ra[4], rb[4];
  auto ldg_tile = [&](int k0) {
    if (MODE == 0) {
#pragma unroll
      for (int u = 0; u < 4; u++) {
        const int j = ja + u * 2;
        const int r = m0 + ia;
        const int bb = r >> 10;       // T = 1024
        const int tt = r & 1023;
        ra[u] = A[(size_t)bb * (Fq * Tq) + (size_t)(k0 + j) * Tq + tt];
        rb[u] = Bm[(size_t)(k0 + j) * NDIM + n0 + ia];
      }
    } else {
      const int row = tid >> 1;
      const int kk = (tid & 1) * 4;
      const float4 av = *(const float4*)&A[(size_t)(m0 + row) * KDIM + k0 + kk];
      ra[0] = av.x; ra[1] = av.y; ra[2] = av.z; ra[3] = av.w;
#pragma unroll
      for (int u = 0; u < 4; u++)
        rb[u] = Bm[(size_t)(k0 + ja + u * 2) * NDIM + n0 + ia];
    }
  };
  auto sts_tile = [&](int buf) {
    if (MODE == 0) {
#pragma unroll
      for (int u = 0; u < 4; u++) {
        sA[buf][ja + u * 2][ia] = ra[u];
        sB[buf][ja + u * 2][ia] = rb[u];
      }
    } else {
      const int row = tid >> 1;
      const int kk = (tid & 1) * 4;
#pragma unroll
      for (int i = 0; i < 4; i++) sA[buf][kk + i][row] = ra[i];
#pragma unroll
      for (int u = 0; u < 4; u++) sB[buf][ja + u * 2][ia] = rb[u];
    }
  };

  u64 acc[8][4];
#pragma unroll
  for (int i = 0; i < 8; i++)
#pragma unroll
    for (int p = 0; p < 4; p++) acc[i][p] = 0ull;

  constexpr int KT = KDIM / 8;
  ldg_tile(0);
  sts_tile(0);
  __syncthreads();

  for (int kt = 0; kt < KT; kt++) {
    const int cur = kt & 1;
    if (kt + 1 < KT) ldg_tile((kt + 1) * 8);
#pragma unroll
    for (int k = 0; k < 8; k++) {
      float a8[8];
      *(float4*)&a8[0] = *(const float4*)&sA[cur][k][ty * 8];
      *(float4*)&a8[4] = *(const float4*)&sA[cur][k][ty * 8 + 4];
      const float4 blo = *(const float4*)&sB[cur][k][tx * 8];
      const float4 bhi = *(const float4*)&sB[cur][k][tx * 8 + 4];
      u64 bp[4];
      bp[0] = pack2(blo.x, blo.y); bp[1] = pack2(blo.z, blo.w);
      bp[2] = pack2(bhi.x, bhi.y); bp[3] = pack2(bhi.z, bhi.w);
#pragma unroll
      for (int i = 0; i < 8; i++) {
        const u64 ai = dup2(a8[i]);
#pragma unroll
        for (int p = 0; p < 4; p++) acc[i][p] = ffma2(ai, bp[p], acc[i][p]);
      }
    }
    if (kt + 1 < KT) {
      sts_tile(1 - cur);
      __syncthreads();
    }
  }

  float bv[8];
#pragma unroll
  for (int j = 0; j < 8; j++) bv[j] = bias[n0 + tx * 8 + j];
#pragma unroll
  for (int i = 0; i < 8; i++) {
    const size_t row = (size_t)(m0 + ty * 8 + i);
    float c[8];
#pragma unroll
    for (int p = 0; p < 4; p++) unpack2(acc[i][p], c[2 * p], c[2 * p + 1]);
    float4 v0, v1;
    v0.x = c[0] + bv[0]; v0.y = c[1] + bv[1];
    v0.z = c[2] + bv[2]; v0.w = c[3] + bv[3];
    v1.x = c[4] + bv[4]; v1.y = c[5] + bv[5];
    v1.z = c[6] + bv[6]; v1.w = c[7] + bv[7];
    *(float4*)&C[row * NDIM + n0 + tx * 8] = v0;
    *(float4*)&C[row * NDIM + n0 + tx * 8 + 4] = v1;
  }
}

// ---------------------------------------------------------------------------
// Persistent recurrent kernel v8 (the 7430us version, reverted verbatim),
// plus ONE final barrier release after the loop to publish S[1023] so the
// streaming phase-3 workers can finish the last t-block.
// ---------------------------------------------------------------------------
__global__ __launch_bounds__(512, 1) void rnn_kernel(const float* __restrict__ Wh) {
  extern __shared__ __align__(16) char smem_dyn[];
  float* sS = (float*)smem_dyn;                              // [16][1024]
  u64 (*sRed)[16][17] = (u64(*)[16][17])(smem_dyn + 65536);  // [16 b][16 pair][17]

  const int tid = threadIdx.x;
  const int lane = tid & 31;
  const int warp = tid >> 5;
  const int g = tid >> 7;           // j-oct group 0..3
  const int w4 = (tid >> 5) & 3;    // warp within group
  const int bblk = blockIdx.x >> 5;         // 0..3  (16 batches each)
  const int jblk = blockIdx.x & 31;         // 0..31 (32 columns each)
  const int j0 = jblk * 32;
  const int jc = j0 + g * 8;        // this group's 8 columns
  const int kt = tid & 127;
  const int k1 = kt * 4, k2 = 512 + kt * 4;
  const int sigma = (lane >> 3) & 3;
  unsigned* bar = &g_barArr[bblk * 32];

  // Register-stationary Wh: rows k1..+3, k2..+3, cols jc..jc+7, sigma-permuted.
  u64 whA[4][4], whB[4][4];
#pragma unroll
  for (int i = 0; i < 4; i++)
#pragma unroll
    for (int p = 0; p < 4; p++) {
      const int q = p ^ sigma;
      const float2 a = *(const float2*)&Wh[(size_t)(k1 + i) * Hq + jc + 2 * q];
      const float2 b = *(const float2*)&Wh[(size_t)(k2 + i) * Hq + jc + 2 * q];
      whA[i][p] = pack2(a.x, a.y);
      whB[i][p] = pack2(b.x, b.y);
    }

  // Output assignment: 1 per thread: batch bblk*16+ob, column j0+oj.
  const int ob = tid >> 5, oj = tid & 31;
  const size_t base_su = (size_t)(bblk * 16 + ob) * (Tq * Hq) + j0 + oj;

  // Staging assignment: warp w stages row w (batch bblk*16+w) via cp.async.
  const int srow = warp;
  const float* gsrc = g_S + (size_t)(bblk * 16 + srow) * (Tq * Hq);
  unsigned sdst[8];
#pragma unroll
  for (int i = 0; i < 8; i++)
    sdst[i] = (unsigned)__cvta_generic_to_shared(&sS[srow * 1024 + lane * 4 + i * 128]);

  unsigned target = GRP;
  auto gbarrier = [&]() {
    __syncthreads();
    if (tid == 0) {
      asm volatile("red.release.gpu.add.u32 [%0], 1;" :: "l"(bar) : "memory");
      unsigned v;
      do {
        asm volatile("ld.acquire.gpu.u32 %0, [%1];" : "=r"(v) : "l"(bar) : "memory");
      } while (v < target);
    }
    __syncthreads();
    target += GRP;
  };

  // One b-round inner product into acc[4] (j-pair p^sigma layout).
  auto inner = [&](const float4& c0, const float4& c1, u64* acc) {
    const u64 s0 = dup2(c0.x);
#pragma unroll
    for (int p = 0; p < 4; p++) acc[p] = fmul2(s0, whA[0][p]);
#pragma unroll
    for (int i = 1; i < 4; i++) {
      const u64 si = dup2(i == 1 ? c0.y : (i == 2 ? c0.z : c0.w));
#pragma unroll
      for (int p = 0; p < 4; p++) acc[p] = ffma2(si, whA[i][p], acc[p]);
    }
#pragma unroll
    for (int i = 0; i < 4; i++) {
      const u64 si = dup2(i == 0 ? c1.x : (i == 1 ? c1.y : (i == 2 ? c1.z : c1.w)));
#pragma unroll
      for (int p = 0; p < 4; p++) acc[p] = ffma2(si, whB[i][p], acc[p]);
    }
  };

  // t = 0 : S0 = tanh(U0)
  __stcg(&g_S[base_su], tanhf(__ldg(&g_U[base_su])));

  for (int t = 1; t < Tq; t++) {
    // Preload U for this thread's output BEFORE the barrier (independent)
    const float uval = __ldg(&g_U[base_su + (size_t)t * Hq]);

    gbarrier();  // this b-group's S[t-1] rows fully written

    // Kick all 16 row copies (8 x 16B per thread, L1-bypass), no registers.
    {
      const float* src = gsrc + (size_t)(t - 1) * Hq;
#pragma unroll
      for (int i = 0; i < 8; i++)
        asm volatile("cp.async.cg.shared.global [%0], [%1], 16;"
                     :: "r"(sdst[i]), "l"(src + lane * 4 + i * 128) : "memory");
      asm volatile("cp.async.commit_group;" ::: "memory");
    }

    // Warps 0-7 (rows 0-7) must land before half-0 compute.
    if (warp < 8) asm volatile("cp.async.wait_group 0;" ::: "memory");
    __syncthreads();

#pragma unroll
    for (int half = 0; half < 2; half++) {
      if (half == 1) {
        if (warp >= 8) asm volatile("cp.async.wait_group 0;" ::: "memory");
        __syncthreads();
      }
#pragma unroll
      for (int pr = 0; pr < 4; pr++) {
        const int bA = half * 8 + pr * 2;
        const int bB = bA + 1;
        const float4 a0 = *(const float4*)&sS[bA * 1024 + k1];
        const float4 a1 = *(const float4*)&sS[bA * 1024 + k2];
        const float4 c0 = *(const float4*)&sS[bB * 1024 + k1];
        const float4 c1 = *(const float4*)&sS[bB * 1024 + k2];

        u64 accA[4], accB[4];
        inner(a0, a1, accA);
        inner(c0, c1, accB);

        // interleaved sel-free sigma-permuted folds (two independent chains)
        u64 rA0 = __shfl_xor_sync(0xffffffffu, accA[2], 16);
        u64 rB0 = __shfl_xor_sync(0xffffffffu, accB[2], 16);
        u64 rA1 = __shfl_xor_sync(0xffffffffu, accA[3], 16);
        u64 rB1 = __shfl_xor_sync(0xffffffffu, accB[3], 16);
        accA[0] = fadd2(accA[0], rA0);
        accB[0] = fadd2(accB[0], rB0);
        accA[1] = fadd2(accA[1], rA1);
        accB[1] = fadd2(accB[1], rB1);
        rA0 = __shfl_xor_sync(0xffffffffu, accA[1], 8);
        rB0 = __shfl_xor_sync(0xffffffffu, accB[1], 8);
        accA[0] = fadd2(accA[0], rA0);
        accB[0] = fadd2(accB[0], rB0);
        rA0 = __shfl_xor_sync(0xffffffffu, accA[0], 4);
        rB0 = __shfl_xor_sync(0xffffffffu, accB[0], 4);
        accA[0] = fadd2(accA[0], rA0);
        accB[0] = fadd2(accB[0], rB0);
        if ((lane & 4) == 0) {
          sRed[bA][g * 4 + sigma][w4 * 4 + (lane & 3)] = accA[0];
          sRed[bB][g * 4 + sigma][w4 * 4 + (lane & 3)] = accB[0];
        }
      }
    }
    __syncthreads();

    // combine: thread sums 8 partials; partner (oj^1) has the other 8.
    {
      const int q = oj >> 1;
      const int h0 = (oj & 1) * 8;
      u64 s0 = fadd2(sRed[ob][q][h0 + 0], sRed[ob][q][h0 + 1]);
      u64 s1 = fadd2(sRed[ob][q][h0 + 2], sRed[ob][q][h0 + 3]);
      u64 s2 = fadd2(sRed[ob][q][h0 + 4], sRed[ob][q][h0 + 5]);
      u64 s3 = fadd2(sRed[ob][q][h0 + 6], sRed[ob][q][h0 + 7]);
      s0 = fadd2(s0, s1); s2 = fadd2(s2, s3);
      s0 = fadd2(s0, s2);
      const u64 other = __shfl_xor_sync(0xffffffffu, s0, 1);
      s0 = fadd2(s0, other);
      float lo, hi;
      unpack2(s0, lo, hi);
      const float dot = (oj & 1) ? hi : lo;
      __stcg(&g_S[base_su + (size_t)t * Hq], tanhf(uval + dot));
    }
  }

  // Publish S[1023]: bar[G] reaches 32*1024 (workers gate on it).
  __syncthreads();
  if (tid == 0)
    asm volatile("red.release.gpu.add.u32 [%0], 1;" :: "l"(bar) : "memory");
}

// ---------------------------------------------------------------------------
// Streaming phase-3 worker: out = S @ Wout + bout via a global tile queue.
// 512 threads, 128x128 tile (4 rows x 8 cols per thread), double-buffered.
// Tile id -> (tb, b, o-block); safe once this b-group's barrier counter
// reaches (tb+1)*4096 (i.e. S rows t < 128*(tb+1) are final).
// Launched twice: 20 CTAs concurrent with the rnn (20 <= 148-128 free SMs,
// so rnn placement can never be blocked -> no deadlock), then 148 CTAs
// after the rnn to drain the rest of the SAME queue.
// ---------------------------------------------------------------------------
__global__ __launch_bounds__(512, 1) void worker_kernel(
    const float* __restrict__ Wout, const float* __restrict__ bout,
    float* __restrict__ out) {
  __shared__ float wA[2][8][128];
  __shared__ float wB[2][8][128];
  __shared__ int sTile;
  const int tid = threadIdx.x;
  const int tx = tid & 15, ty = tid >> 4;          // ty 0..31
  const int ia = tid & 127, jb = tid >> 7;         // B-load lanes
  const int arow = tid >> 1, akk = (tid & 1) * 4;  // A-load lanes (tid<256)

  for (;;) {
    __syncthreads();   // protect smem/sTile from previous tile
    if (tid == 0) sTile = (int)atomicAdd(&g_tile, 1u);
    __syncthreads();
    const int id = sTile;
    if (id >= NTILES) return;

    const int tb = id >> 8;           // t-block 0..7 (128 steps each)
    const int rem = id & 255;
    const int bb = rem >> 2;          // batch 0..63
    const int o0 = (rem & 3) * 128;   // output-column block
    const size_t r0 = (size_t)bb * Tq + (size_t)tb * 128;

    if (tid == 0) {   // wait until S rows for this t-block are final
      unsigned* bar = &g_barArr[(bb >> 4) * 32];
      const unsigned need = (unsigned)(tb + 1) * 4096u;
      unsigned v;
      for (;;) {
        asm volatile("ld.acquire.gpu.u32 %0, [%1];" : "=r"(v) : "l"(bar) : "memory");
        if (v >= need) break;
        __nanosleep(1000);
      }
    }
    __syncthreads();

    u64 acc[4][4];
#pragma unroll
    for (int i = 0; i < 4; i++)
#pragma unroll
      for (int p = 0; p < 4; p++) acc[i][p] = 0ull;

    float4 raA;
    float rb0, rb1;
    auto ldg_tile = [&](int k0) {
      if (tid < 256)
        raA = __ldcg((const float4*)&g_S[(r0 + arow) * Hq + k0 + akk]);
      rb0 = Wout[(size_t)(k0 + jb) * Oq + o0 + ia];
      rb1 = Wout[(size_t)(k0 + jb + 4) * Oq + o0 + ia];
    };
    auto sts_tile = [&](int buf) {
      if (tid < 256) {
        wA[buf][akk + 0][arow] = raA.x;
        wA[buf][akk + 1][arow] = raA.y;
        wA[buf][akk + 2][arow] = raA.z;
        wA[buf][akk + 3][arow] = raA.w;
      }
      wB[buf][jb][ia] = rb0;
      wB[buf][jb + 4][ia] = rb1;
    };

    constexpr int KT = Hq / 8;  // 128 k-tiles
    ldg_tile(0);
    sts_tile(0);
    __syncthreads();

    for (int kti = 0; kti < KT; kti++) {
      const int cur = kti & 1;
      if (kti + 1 < KT) ldg_tile((kti + 1) * 8);
#pragma unroll
      for (int k = 0; k < 8; k++) {
        float a4[4];
        *(float4*)&a4[0] = *(const float4*)&wA[cur][k][ty * 4];
        const float4 blo = *(const float4*)&wB[cur][k][tx * 8];
        const float4 bhi = *(const float4*)&wB[cur][k][tx * 8 + 4];
        u64 bp[4];
        bp[0] = pack2(blo.x, blo.y); bp[1] = pack2(blo.z, blo.w);
        bp[2] = pack2(bhi.x, bhi.y); bp[3] = pack2(bhi.z, bhi.w);
#pragma unroll
        for (int i = 0; i < 4; i++) {
          const u64 ai = dup2(a4[i]);
#pragma unroll
          for (int p = 0; p < 4; p++) acc[i][p] = ffma2(ai, bp[p], acc[i][p]);
        }
      }
      if (kti + 1 < KT) {
        sts_tile(1 - cur);
        __syncthreads();
      }
    }

    float bv[8];
#pragma unroll
    for (int j = 0; j < 8; j++) bv[j] = bout[o0 + tx * 8 + j];
#pragma unroll
    for (int i = 0; i < 4; i++) {
      const size_t row = r0 + ty * 4 + i;
      float c[8];
#pragma unroll
      for (int p = 0; p < 4; p++) unpack2(acc[i][p], c[2 * p], c[2 * p + 1]);
      float4 v0, v1;
      v0.x = c[0] + bv[0]; v0.y = c[1] + bv[1];
      v0.z = c[2] + bv[2]; v0.w = c[3] + bv[3];
      v1.x = c[4] + bv[4]; v1.y = c[5] + bv[5];
      v1.z = c[6] + bv[6]; v1.w = c[7] + bv[7];
      *(float4*)&out[row * Oq + o0 + tx * 8] = v0;
      *(float4*)&out[row * Oq + o0 + tx * 8 + 4] = v1;
    }
  }
}

extern "C" void kernel_launch(void* const* d_in, const int* in_sizes, int n_in,
                              void* d_out, int out_size) {
  const float* x    = (const float*)d_in[0];
  const float* Wx   = (const float*)d_in[1];
  const float* Wh   = (const float*)d_in[2];
  const float* bv   = (const float*)d_in[3];
  const float* Wout = (const float*)d_in[4];
  const float* bout = (const float*)d_in[5];
  float* out = (float*)d_out;

  float* U = nullptr;
  cudaGetSymbolAddress((void**)&U, g_U);

  constexpr int RNN_SMEM = 65536 + 16 * 16 * 17 * 8;  // 100352 B
  static cudaStream_t s_side = nullptr;
  static cudaEvent_t evA = nullptr, evW = nullptr;
  static bool init_done = false;
  if (!init_done) {
    cudaFuncSetAttribute(rnn_kernel,
                         cudaFuncAttributeMaxDynamicSharedMemorySize, RNN_SMEM);
    cudaStreamCreateWithFlags(&s_side, cudaStreamNonBlocking);
    cudaEventCreateWithFlags(&evA, cudaEventDisableTiming);
    cudaEventCreateWithFlags(&evW, cudaEventDisableTiming);
    init_done = true;
  }

  reset_kernel<<<1, 256>>>();
  // Phase 1: U = x @ Wx + b   (M = B*T = 65536, K = 256, N = 1024)
  gemm_bias_kernel<0, Fq, Hq><<<dim3(Hq / 128, (Bq * Tq) / 128), 256>>>(x, Wx, bv, U);
  // Launch-slot shim: keeps the rnn in the ncu-captured launch position.
  dummy_kernel<<<1, 1>>>();
  // Fork point: rnn (main stream) and 20 streaming workers (side stream)
  // run concurrently; workers gate on the rnn's barrier counters.
  cudaEventRecord(evA, 0);
  rnn_kernel<<<NB_RNN, 512, RNN_SMEM>>>(Wh);
  cudaStreamWaitEvent(s_side, evA, 0);
  worker_kernel<<<20, 512, 0, s_side>>>(Wout, bout, out);
  cudaEventRecord(evW, s_side);
  // After the rnn: drain the remaining queue at full chip.
  worker_kernel<<<148, 512>>>(Wout, bout, out);
  cudaStreamWaitEvent(0, evW, 0);  // join side branch before graph end
}

// round 16
// speedup vs baseline: 1.1259x; 1.1259x over previous
#include <cuda_runtime.h>
#include <math.h>

constexpr int Bq = 64, Fq = 256, Tq = 1024, Hq = 1024, Oq = 512;
constexpr int NB_RNN = 128;
constexpr int GRP = 32;       // CTAs per b-group barrier

// Scratch (allocations forbidden; __device__ globals are the sanctioned path)
__device__ float g_U[(size_t)Bq * Tq * Hq];   // (B, T, H) = x@Wx + b
__device__ float g_S[(size_t)Bq * Tq * Hq];   // (B, T, H) states
__device__ unsigned g_barArr[4 * 32];         // 4 group barriers, 128B apart

__global__ void reset_kernel() {
  if (threadIdx.x < 4 * 32) g_barArr[threadIdx.x] = 0u;
}
__global__ void dummy_kernel() {}  // keeps rnn in ncu's captured launch slot

// ---------------- packed fp32x2 helpers (sm_103a FFMA2 path) ----------------
using u64 = unsigned long long;
__device__ __forceinline__ u64 pack2(float lo, float hi) {
  u64 r; asm("mov.b64 %0, {%1,%2};" : "=l"(r) : "f"(lo), "f"(hi)); return r;
}
__device__ __forceinline__ u64 dup2(float v) { return pack2(v, v); }
__device__ __forceinline__ u64 ffma2(u64 a, u64 b, u64 c) {
  u64 d; asm("fma.rn.f32x2 %0, %1, %2, %3;" : "=l"(d) : "l"(a), "l"(b), "l"(c));
  return d;
}
__device__ __forceinline__ u64 fmul2(u64 a, u64 b) {
  u64 d; asm("mul.rn.f32x2 %0, %1, %2;" : "=l"(d) : "l"(a), "l"(b)); return d;
}
__device__ __forceinline__ u64 fadd2(u64 a, u64 b) {
  u64 d; asm("add.rn.f32x2 %0, %1, %2;" : "=l"(d) : "l"(a), "l"(b)); return d;
}
__device__ __forceinline__ void unpack2(u64 v, float& lo, float& hi) {
  asm("mov.b64 {%0,%1}, %2;" : "=f"(lo), "=f"(hi) : "l"(v));
}

// ---------------------------------------------------------------------------
// Phase-1 GEMM: U = x@Wx + b (known good since R5).  128x128 tile, 8x8
// thread tile, double-buffered.  A[r][f] = x[b,f,t] gather (coalesced on t).
// ---------------------------------------------------------------------------
__global__ __launch_bounds__(256, 2) void gemm_p1_kernel(
    const float* __restrict__ A, const float* __restrict__ Bm,
    const float* __restrict__ bias, float* __restrict__ C) {
  constexpr int KDIM = Fq, NDIM = Hq;
  __shared__ float sA[2][8][128];
  __shared__ float sB[2][8][128];
  const int tid = threadIdx.x;
  const int n0 = blockIdx.x * 128;
  const int m0 = blockIdx.y * 128;
  const int tx = tid & 15, ty = tid >> 4;
  const int ia = tid & 127, ja = tid >> 7;

  float ra[4], rb[4];
  auto ldg_tile = [&](int k0) {
#pragma unroll
    for (int u = 0; u < 4; u++) {
      const int j = ja + u * 2;
      const int r = m0 + ia;
      const int bb = r >> 10;       // T = 1024
      const int tt = r & 1023;
      ra[u] = A[(size_t)bb * (Fq * Tq) + (size_t)(k0 + j) * Tq + tt];
      rb[u] = Bm[(size_t)(k0 + j) * NDIM + n0 + ia];
    }
  };
  auto sts_tile = [&](int buf) {
#pragma unroll
    for (int u = 0; u < 4; u++) {
      sA[buf][ja + u * 2][ia] = ra[u];
      sB[buf][ja + u * 2][ia] = rb[u];
    }
  };

  u64 acc[8][4];
#pragma unroll
  for (int i = 0; i < 8; i++)
#pragma unroll
    for (int p = 0; p < 4; p++) acc[i][p] = 0ull;

  constexpr int KT = KDIM / 8;
  ldg_tile(0);
  sts_tile(0);
  __syncthreads();

  for (int kt = 0; kt < KT; kt++) {
    const int cur = kt & 1;
    if (kt + 1 < KT) ldg_tile((kt + 1) * 8);
#pragma unroll
    for (int k = 0; k < 8; k++) {
      float a8[8];
      *(float4*)&a8[0] = *(const float4*)&sA[cur][k][ty * 8];
      *(float4*)&a8[4] = *(const float4*)&sA[cur][k][ty * 8 + 4];
      const float4 blo = *(const float4*)&sB[cur][k][tx * 8];
      const float4 bhi = *(const float4*)&sB[cur][k][tx * 8 + 4];
      u64 bp[4];
      bp[0] = pack2(blo.x, blo.y); bp[1] = pack2(blo.z, blo.w);
      bp[2] = pack2(bhi.x, bhi.y); bp[3] = pack2(bhi.z, bhi.w);
#pragma unroll
      for (int i = 0; i < 8; i++) {
        const u64 ai = dup2(a8[i]);
#pragma unroll
        for (int p = 0; p < 4; p++) acc[i][p] = ffma2(ai, bp[p], acc[i][p]);
      }
    }
    if (kt + 1 < KT) {
      sts_tile(1 - cur);
      __syncthreads();
    }
  }

  float bv[8];
#pragma unroll
  for (int j = 0; j < 8; j++) bv[j] = bias[n0 + tx * 8 + j];
#pragma unroll
  for (int i = 0; i < 8; i++) {
    const size_t row = (size_t)(m0 + ty * 8 + i);
    float c[8];
#pragma unroll
    for (int p = 0; p < 4; p++) unpack2(acc[i][p], c[2 * p], c[2 * p + 1]);
    float4 v0, v1;
    v0.x = c[0] + bv[0]; v0.y = c[1] + bv[1];
    v0.z = c[2] + bv[2]; v0.w = c[3] + bv[3];
    v1.x = c[4] + bv[4]; v1.y = c[5] + bv[5];
    v1.z = c[6] + bv[6]; v1.w = c[7] + bv[7];
    *(float4*)&C[row * NDIM + n0 + tx * 8] = v0;
    *(float4*)&C[row * NDIM + n0 + tx * 8 + 4] = v1;
  }
}

// ---------------------------------------------------------------------------
// Phase-3 GEMM v2: out = S @ Wout + bout.  CROSSBAR-RELIEVED tiling:
// 128 threads/CTA, 128x128 CTA tile, 16x8 thread tile (16 acc rows x 4
// f32x2 col-pairs).  Crossbar bytes per MAC drop 1.33x vs 8x8 and, more
// importantly, per-SM crossbar demand falls below the 128 B/cyc cap
// (R8 profile: L1=93.3% crossbar-bound, fma capped at 62%).
// launch_bounds(128,2): ~180 regs OK, 2 CTAs x 4 warps per SM.
// A row-major [M,K]: thread loads its own row's 8 k-floats (32B, sector-
// aligned); B: thread loads one float per k-row (coalesced 512B rows).
// ---------------------------------------------------------------------------
__global__ __launch_bounds__(128, 2) void gemm_out_kernel(
    const float* __restrict__ A, const float* __restrict__ Bm,
    const float* __restrict__ bias, float* __restrict__ C) {
  constexpr int KDIM = Hq, NDIM = Oq;
  __shared__ float sA[2][8][128];
  __shared__ float sB[2][8][128];
  const int tid = threadIdx.x;
  const int n0 = blockIdx.x * 128;
  const int m0 = blockIdx.y * 128;
  const int tx = tid & 15, ty = tid >> 4;   // tx 0..15 (8 cols), ty 0..7 (16 rows)

  float4 ra0, ra1;
  float rb[8];
  auto ldg_tile = [&](int k0) {
    const float* ap = &A[(size_t)(m0 + tid) * KDIM + k0];
    ra0 = *(const float4*)(ap);
    ra1 = *(const float4*)(ap + 4);
#pragma unroll
    for (int j = 0; j < 8; j++)
      rb[j] = Bm[(size_t)(k0 + j) * NDIM + n0 + tid];
  };
  auto sts_tile = [&](int buf) {
    sA[buf][0][tid] = ra0.x; sA[buf][1][tid] = ra0.y;
    sA[buf][2][tid] = ra0.z; sA[buf][3][tid] = ra0.w;
    sA[buf][4][tid] = ra1.x; sA[buf][5][tid] = ra1.y;
    sA[buf][6][tid] = ra1.z; sA[buf][7][tid] = ra1.w;
#pragma unroll
    for (int j = 0; j < 8; j++) sB[buf][j][tid] = rb[j];
  };

  u64 acc[16][4];
#pragma unroll
  for (int i = 0; i < 16; i++)
#pragma unroll
    for (int p = 0; p < 4; p++) acc[i][p] = 0ull;

  constexpr int KT = KDIM / 8;  // 128 k-tiles
  ldg_tile(0);
  sts_tile(0);
  __syncthreads();

  for (int kt = 0; kt < KT; kt++) {
    const int cur = kt & 1;
    if (kt + 1 < KT) ldg_tile((kt + 1) * 8);
#pragma unroll
    for (int k = 0; k < 8; k++) {
      float a16[16];
      *(float4*)&a16[0]  = *(const float4*)&sA[cur][k][ty * 16];
      *(float4*)&a16[4]  = *(const float4*)&sA[cur][k][ty * 16 + 4];
      *(float4*)&a16[8]  = *(const float4*)&sA[cur][k][ty * 16 + 8];
      *(float4*)&a16[12] = *(const float4*)&sA[cur][k][ty * 16 + 12];
      const float4 blo = *(const float4*)&sB[cur][k][tx * 8];
      const float4 bhi = *(const float4*)&sB[cur][k][tx * 8 + 4];
      u64 bp[4];
      bp[0] = pack2(blo.x, blo.y); bp[1] = pack2(blo.z, blo.w);
      bp[2] = pack2(bhi.x, bhi.y); bp[3] = pack2(bhi.z, bhi.w);
#pragma unroll
      for (int i = 0; i < 16; i++) {
        const u64 ai = dup2(a16[i]);
#pragma unroll
        for (int p = 0; p < 4; p++) acc[i][p] = ffma2(ai, bp[p], acc[i][p]);
      }
    }
    if (kt + 1 < KT) {
      sts_tile(1 - cur);
      __syncthreads();
    }
  }

  float bv[8];
#pragma unroll
  for (int j = 0; j < 8; j++) bv[j] = bias[n0 + tx * 8 + j];
#pragma unroll
  for (int i = 0; i < 16; i++) {
    const size_t row = (size_t)(m0 + ty * 16 + i);
    float c[8];
#pragma unroll
    for (int p = 0; p < 4; p++) unpack2(acc[i][p], c[2 * p], c[2 * p + 1]);
    float4 v0, v1;
    v0.x = c[0] + bv[0]; v0.y = c[1] + bv[1];
    v0.z = c[2] + bv[2]; v0.w = c[3] + bv[3];
    v1.x = c[4] + bv[4]; v1.y = c[5] + bv[5];
    v1.z = c[6] + bv[6]; v1.w = c[7] + bv[7];
    *(float4*)&C[row * NDIM + n0 + tx * 8] = v0;
    *(float4*)&C[row * NDIM + n0 + tx * 8 + 4] = v1;
  }
}

// ---------------------------------------------------------------------------
// Persistent recurrent kernel v8 (the 7430us version, verbatim).
// ---------------------------------------------------------------------------
__global__ __launch_bounds__(512, 1) void rnn_kernel(const float* __restrict__ Wh) {
  extern __shared__ __align__(16) char smem_dyn[];
  float* sS = (float*)smem_dyn;                              // [16][1024]
  u64 (*sRed)[16][17] = (u64(*)[16][17])(smem_dyn + 65536);  // [16 b][16 pair][17]

  const int tid = threadIdx.x;
  const int lane = tid & 31;
  const int warp = tid >> 5;
  const int g = tid >> 7;           // j-oct group 0..3
  const int w4 = (tid >> 5) & 3;    // warp within group
  const int bblk = blockIdx.x >> 5;         // 0..3  (16 batches each)
  const int jblk = blockIdx.x & 31;         // 0..31 (32 columns each)
  const int j0 = jblk * 32;
  const int jc = j0 + g * 8;        // this group's 8 columns
  const int kt = tid & 127;
  const int k1 = kt * 4, k2 = 512 + kt * 4;
  const int sigma = (lane >> 3) & 3;
  unsigned* bar = &g_barArr[bblk * 32];

  // Register-stationary Wh: rows k1..+3, k2..+3, cols jc..jc+7, sigma-permuted.
  u64 whA[4][4], whB[4][4];
#pragma unroll
  for (int i = 0; i < 4; i++)
#pragma unroll
    for (int p = 0; p < 4; p++) {
      const int q = p ^ sigma;
      const float2 a = *(const float2*)&Wh[(size_t)(k1 + i) * Hq + jc + 2 * q];
      const float2 b = *(const float2*)&Wh[(size_t)(k2 + i) * Hq + jc + 2 * q];
      whA[i][p] = pack2(a.x, a.y);
      whB[i][p] = pack2(b.x, b.y);
    }

  // Output assignment: 1 per thread: batch bblk*16+ob, column j0+oj.
  const int ob = tid >> 5, oj = tid & 31;
  const size_t base_su = (size_t)(bblk * 16 + ob) * (Tq * Hq) + j0 + oj;

  // Staging assignment: warp w stages row w (batch bblk*16+w) via cp.async.
  const int srow = warp;
  const float* gsrc = g_S + (size_t)(bblk * 16 + srow) * (Tq * Hq);
  unsigned sdst[8];
#pragma unroll
  for (int i = 0; i < 8; i++)
    sdst[i] = (unsigned)__cvta_generic_to_shared(&sS[srow * 1024 + lane * 4 + i * 128]);

  unsigned target = GRP;
  auto gbarrier = [&]() {
    __syncthreads();
    if (tid == 0) {
      asm volatile("red.release.gpu.add.u32 [%0], 1;" :: "l"(bar) : "memory");
      unsigned v;
      do {
        asm volatile("ld.acquire.gpu.u32 %0, [%1];" : "=r"(v) : "l"(bar) : "memory");
      } while (v < target);
    }
    __syncthreads();
    target += GRP;
  };

  // One b-round inner product into acc[4] (j-pair p^sigma layout).
  auto inner = [&](const float4& c0, const float4& c1, u64* acc) {
    const u64 s0 = dup2(c0.x);
#pragma unroll
    for (int p = 0; p < 4; p++) acc[p] = fmul2(s0, whA[0][p]);
#pragma unroll
    for (int i = 1; i < 4; i++) {
      const u64 si = dup2(i == 1 ? c0.y : (i == 2 ? c0.z : c0.w));
#pragma unroll
      for (int p = 0; p < 4; p++) acc[p] = ffma2(si, whA[i][p], acc[p]);
    }
#pragma unroll
    for (int i = 0; i < 4; i++) {
      const u64 si = dup2(i == 0 ? c1.x : (i == 1 ? c1.y : (i == 2 ? c1.z : c1.w)));
#pragma unroll
      for (int p = 0; p < 4; p++) acc[p] = ffma2(si, whB[i][p], acc[p]);
    }
  };

  // t = 0 : S0 = tanh(U0)
  __stcg(&g_S[base_su], tanhf(__ldg(&g_U[base_su])));

  for (int t = 1; t < Tq; t++) {
    // Preload U for this thread's output BEFORE the barrier (independent)
    const float uval = __ldg(&g_U[base_su + (size_t)t * Hq]);

    gbarrier();  // this b-group's S[t-1] rows fully written

    // Kick all 16 row copies (8 x 16B per thread, L1-bypass), no registers.
    {
      const float* src = gsrc + (size_t)(t - 1) * Hq;
#pragma unroll
      for (int i = 0; i < 8; i++)
        asm volatile("cp.async.cg.shared.global [%0], [%1], 16;"
                     :: "r"(sdst[i]), "l"(src + lane * 4 + i * 128) : "memory");
      asm volatile("cp.async.commit_group;" ::: "memory");
    }

    // Warps 0-7 (rows 0-7) must land before half-0 compute.
    if (warp < 8) asm volatile("cp.async.wait_group 0;" ::: "memory");
    __syncthreads();

#pragma unroll
    for (int half = 0; half < 2; half++) {
      if (half == 1) {
        if (warp >= 8) asm volatile("cp.async.wait_group 0;" ::: "memory");
        __syncthreads();
      }
#pragma unroll
      for (int pr = 0; pr < 4; pr++) {
        const int bA = half * 8 + pr * 2;
        const int bB = bA + 1;
        const float4 a0 = *(const float4*)&sS[bA * 1024 + k1];
        const float4 a1 = *(const float4*)&sS[bA * 1024 + k2];
        const float4 c0 = *(const float4*)&sS[bB * 1024 + k1];
        const float4 c1 = *(const float4*)&sS[bB * 1024 + k2];

        u64 accA[4], accB[4];
        inner(a0, a1, accA);
        inner(c0, c1, accB);

        // interleaved sel-free sigma-permuted folds (two independent chains)
        u64 rA0 = __shfl_xor_sync(0xffffffffu, accA[2], 16);
        u64 rB0 = __shfl_xor_sync(0xffffffffu, accB[2], 16);
        u64 rA1 = __shfl_xor_sync(0xffffffffu, accA[3], 16);
        u64 rB1 = __shfl_xor_sync(0xffffffffu, accB[3], 16);
        accA[0] = fadd2(accA[0], rA0);
        accB[0] = fadd2(accB[0], rB0);
        accA[1] = fadd2(accA[1], rA1);
        accB[1] = fadd2(accB[1], rB1);
        rA0 = __shfl_xor_sync(0xffffffffu, accA[1], 8);
        rB0 = __shfl_xor_sync(0xffffffffu, accB[1], 8);
        accA[0] = fadd2(accA[0], rA0);
        accB[0] = fadd2(accB[0], rB0);
        rA0 = __shfl_xor_sync(0xffffffffu, accA[0], 4);
        rB0 = __shfl_xor_sync(0xffffffffu, accB[0], 4);
        accA[0] = fadd2(accA[0], rA0);
        accB[0] = fadd2(accB[0], rB0);
        if ((lane & 4) == 0) {
          sRed[bA][g * 4 + sigma][w4 * 4 + (lane & 3)] = accA[0];
          sRed[bB][g * 4 + sigma][w4 * 4 + (lane & 3)] = accB[0];
        }
      }
    }
    __syncthreads();

    // combine: thread sums 8 partials; partner (oj^1) has the other 8.
    {
      const int q = oj >> 1;
      const int h0 = (oj & 1) * 8;
      u64 s0 = fadd2(sRed[ob][q][h0 + 0], sRed[ob][q][h0 + 1]);
      u64 s1 = fadd2(sRed[ob][q][h0 + 2], sRed[ob][q][h0 + 3]);
      u64 s2 = fadd2(sRed[ob][q][h0 + 4], sRed[ob][q][h0 + 5]);
      u64 s3 = fadd2(sRed[ob][q][h0 + 6], sRed[ob][q][h0 + 7]);
      s0 = fadd2(s0, s1); s2 = fadd2(s2, s3);
      s0 = fadd2(s0, s2);
      const u64 other = __shfl_xor_sync(0xffffffffu, s0, 1);
      s0 = fadd2(s0, other);
      float lo, hi;
      unpack2(s0, lo, hi);
      const float dot = (oj & 1) ? hi : lo;
      __stcg(&g_S[base_su + (size_t)t * Hq], tanhf(uval + dot));
    }
  }
}

extern "C" void kernel_launch(void* const* d_in, const int* in_sizes, int n_in,
                              void* d_out, int out_size) {
  const float* x    = (const float*)d_in[0];
  const float* Wx   = (const float*)d_in[1];
  const float* Wh   = (const float*)d_in[2];
  const float* bv   = (const float*)d_in[3];
  const float* Wout = (const float*)d_in[4];
  const float* bout = (const float*)d_in[5];
  float* out = (float*)d_out;

  float* U = nullptr;
  float* S = nullptr;
  cudaGetSymbolAddress((void**)&U, g_U);
  cudaGetSymbolAddress((void**)&S, g_S);

  constexpr int RNN_SMEM = 65536 + 16 * 16 * 17 * 8;  // 100352 B
  static bool attr_set = false;
  if (!attr_set) {
    cudaFuncSetAttribute(rnn_kernel,
                         cudaFuncAttributeMaxDynamicSharedMemorySize, RNN_SMEM);
    attr_set = true;
  }

  reset_kernel<<<1, 128>>>();
  // Phase 1: U = x @ Wx + b   (M = B*T = 65536, K = 256, N = 1024)
  gemm_p1_kernel<<<dim3(Hq / 128, (Bq * Tq) / 128), 256>>>(x, Wx, bv, U);
  // Launch-slot shim: keeps the rnn in the ncu-captured launch position.
  dummy_kernel<<<1, 1>>>();
  // Phase 2: sequential recurrence, persistent cooperative kernel
  rnn_kernel<<<NB_RNN, 512, RNN_SMEM>>>(Wh);
  // Phase 3: out = states @ Wout + bout  (M = 65536, K = 1024, N = 512)
  // 16x8 register tile, crossbar-relieved.
  gemm_out_kernel<<<dim3(Oq / 128, (Bq * Tq) / 128), 128>>>(S, Wout, bout, out);
}